// round 7
// baseline (speedup 1.0000x reference)
#include <cuda_runtime.h>
#include <cuda_bf16.h>
#include <math.h>

#define S_LEN 512
#define BSZ   128
#define EDIM  300
#define HDIM  256
#define NCLS  6
#define PDIM  256
#define NCTA_LSTM 128            // 64 u-slices x 2 dirs, all co-resident (<148 SMs)

// ---------------- scratch (device globals; no runtime allocation) ----------
__device__ float g_seq_emb[(size_t)S_LEN * BSZ * EDIM];              // 78.6 MB
__device__ float g_gx[2][(size_t)S_LEN * 4 * HDIM * BSZ];            // [dir][s][col][b] 536 MB
__device__ float g_h[2][2][HDIM][BSZ];                               // [dir][buf][u][b] 512 KB
__device__ float g_h0[(size_t)BSZ * 2 * HDIM];                       // concat [fh, bh]
__device__ float g_gxc[NCLS * 3 * 2 * HDIM];                         // decoder input gates
__device__ float g_Wt4[2][HDIM][HDIM][4];                            // [dir][k][u][gate i,f,g,o]
__device__ float g_dWt4[2 * HDIM][2 * HDIM][4];                      // [k][u][gate r,z,n,pad]
__device__ int   g_bar_cnt;                                          // barrier arrivals
__device__ volatile int g_flags[NCTA_LSTM][32];                      // per-CTA release lines (128B)

// ---------------- helpers ---------------------------------------------------
__device__ __forceinline__ float sigmoidf_(float x) { return 1.0f / (1.0f + expf(-x)); }
__device__ __forceinline__ float tanhf_(float x) { return 1.0f - 2.0f / (expf(2.0f * x) + 1.0f); }

__device__ __forceinline__ unsigned long long pk2(float lo, float hi) {
    return ((unsigned long long)__float_as_uint(hi) << 32) | (unsigned long long)__float_as_uint(lo);
}
__device__ __forceinline__ float2 upk2(unsigned long long u) {
    float2 f; f.x = __uint_as_float((unsigned)u); f.y = __uint_as_float((unsigned)(u >> 32)); return f;
}
__device__ __forceinline__ void fma2(unsigned long long& d, unsigned long long a, unsigned long long b) {
    asm("fma.rn.f32x2 %0, %1, %2, %0;" : "+l"(d) : "l"(a), "l"(b));
}

// ---------------- kernel 0a: transpose LSTM Whh + reset barrier -------------
__global__ __launch_bounds__(1024) void transpose_lstm_w(const float* __restrict__ fWhh,
                                                         const float* __restrict__ bWhh)
{
    if (blockIdx.x == 0 && blockIdx.y == 0 && blockIdx.z == 0) {
        if (threadIdx.x == 0) g_bar_cnt = 0;
        for (int i = threadIdx.x; i < NCTA_LSTM * 32; i += 1024)
            ((int*)g_flags)[i] = 0;
    }
    __shared__ float t[32][33];
    const int dir = blockIdx.z >> 2;
    const int g   = blockIdx.z & 3;
    const int k0  = blockIdx.x * 32;
    const int u0  = blockIdx.y * 32;
    const int tx = threadIdx.x & 31, ty = threadIdx.x >> 5;
    const float* W = dir ? bWhh : fWhh;
    t[ty][tx] = W[(size_t)(g * HDIM + u0 + ty) * HDIM + k0 + tx];
    __syncthreads();
    g_Wt4[dir][k0 + ty][u0 + tx][g] = t[tx][ty];
}

// ---------------- kernel 0b: transpose decoder Whh ---------------------------
__global__ __launch_bounds__(1024) void transpose_dec_w(const float* __restrict__ dWhh)
{
    __shared__ float t[32][33];
    const int g  = blockIdx.z;
    const int k0 = blockIdx.x * 32;
    const int u0 = blockIdx.y * 32;
    const int tx = threadIdx.x & 31, ty = threadIdx.x >> 5;
    t[ty][tx] = dWhh[(size_t)(g * 2 * HDIM + u0 + ty) * (2 * HDIM) + k0 + tx];
    __syncthreads();
    g_dWt4[k0 + ty][u0 + tx][g] = t[tx][ty];
}

// ---------------- kernel 1: embedding gather + tanh, time-major -------------
__global__ void embed_kernel(const int* __restrict__ seq, const float* __restrict__ embW) {
    long long idx = (long long)blockIdx.x * blockDim.x + threadIdx.x;
    const long long total = (long long)S_LEN * BSZ * EDIM;
    if (idx >= total) return;
    int e = (int)(idx % EDIM);
    int r = (int)(idx / EDIM);
    int b = r % BSZ;
    int s = r / BSZ;
    int v = seq[b * S_LEN + s];
    g_seq_emb[idx] = tanhf_(embW[(long long)v * EDIM + e]);
}

// ---------------- kernel 2: input GEMMs, double-buffered smem ---------------
__global__ __launch_bounds__(256) void gx_gemm_kernel(
    const float* __restrict__ fWih, const float* __restrict__ fbih, const float* __restrict__ fbhh,
    const float* __restrict__ bWih, const float* __restrict__ bbih, const float* __restrict__ bbhh)
{
    __shared__ float As[2][16][128];
    __shared__ float Bs[2][16][128];

    const int dir   = blockIdx.z;
    const int s     = blockIdx.x;
    const int ntile = blockIdx.y;
    const float* W  = dir ? bWih : fWih;
    const float* bi = dir ? bbih : fbih;
    const float* bh = dir ? bbhh : fbhh;
    const int src_s = dir ? ((S_LEN - s) & (S_LEN - 1)) : s;
    const float* Abase = g_seq_emb + (size_t)src_s * BSZ * EDIM;

    const int t   = threadIdx.x;
    const int lr  = t & 127;
    const int lqp = t >> 7;
    const int tm  = t >> 4;
    const int tn  = t & 15;

    unsigned long long acc2[8][4];
#pragma unroll
    for (int i = 0; i < 8; i++)
#pragma unroll
        for (int j = 0; j < 4; j++) acc2[i][j] = 0ULL;

    const int NK = (EDIM + 15) / 16;   // 19
    float4 av[2], bv[2];
#pragma unroll
    for (int q = 0; q < 2; q++) {
        const int kk = (lqp * 2 + q) * 4;
        av[q] = make_float4(0.f, 0.f, 0.f, 0.f);
        bv[q] = make_float4(0.f, 0.f, 0.f, 0.f);
        if (kk + 3 < EDIM) {
            av[q] = *(const float4*)(W + (size_t)(ntile * 128 + lr) * EDIM + kk);
            bv[q] = *(const float4*)(Abase + (size_t)lr * EDIM + kk);
        }
    }
#pragma unroll
    for (int q = 0; q < 2; q++) {
        const int kb = (lqp * 2 + q) * 4;
        As[0][kb + 0][lr] = av[q].x; As[0][kb + 1][lr] = av[q].y;
        As[0][kb + 2][lr] = av[q].z; As[0][kb + 3][lr] = av[q].w;
        Bs[0][kb + 0][lr] = bv[q].x; Bs[0][kb + 1][lr] = bv[q].y;
        Bs[0][kb + 2][lr] = bv[q].z; Bs[0][kb + 3][lr] = bv[q].w;
    }

    for (int kt = 0; kt < NK; kt++) {
        __syncthreads();
        const int cur = kt & 1;
        const bool more = (kt + 1 < NK);
        if (more) {
#pragma unroll
            for (int q = 0; q < 2; q++) {
                const int kk = (kt + 1) * 16 + (lqp * 2 + q) * 4;
                av[q] = make_float4(0.f, 0.f, 0.f, 0.f);
                bv[q] = make_float4(0.f, 0.f, 0.f, 0.f);
                if (kk + 3 < EDIM) {
                    av[q] = *(const float4*)(W + (size_t)(ntile * 128 + lr) * EDIM + kk);
                    bv[q] = *(const float4*)(Abase + (size_t)lr * EDIM + kk);
                }
            }
        }
#pragma unroll
        for (int k = 0; k < 16; k++) {
            float4 aA = *(const float4*)&As[cur][k][tm * 8];
            float4 aB = *(const float4*)&As[cur][k][tm * 8 + 4];
            ulonglong2 bA = *(const ulonglong2*)&Bs[cur][k][4 * tn];
            ulonglong2 bB = *(const ulonglong2*)&Bs[cur][k][64 + 4 * tn];
            unsigned long long a[8];
            a[0] = pk2(aA.x, aA.x); a[1] = pk2(aA.y, aA.y);
            a[2] = pk2(aA.z, aA.z); a[3] = pk2(aA.w, aA.w);
            a[4] = pk2(aB.x, aB.x); a[5] = pk2(aB.y, aB.y);
            a[6] = pk2(aB.z, aB.z); a[7] = pk2(aB.w, aB.w);
#pragma unroll
            for (int i = 0; i < 8; i++) {
                fma2(acc2[i][0], a[i], bA.x);
                fma2(acc2[i][1], a[i], bA.y);
                fma2(acc2[i][2], a[i], bB.x);
                fma2(acc2[i][3], a[i], bB.y);
            }
        }
        if (more) {
            const int nxt = cur ^ 1;
#pragma unroll
            for (int q = 0; q < 2; q++) {
                const int kb = (lqp * 2 + q) * 4;
                As[nxt][kb + 0][lr] = av[q].x; As[nxt][kb + 1][lr] = av[q].y;
                As[nxt][kb + 2][lr] = av[q].z; As[nxt][kb + 3][lr] = av[q].w;
                Bs[nxt][kb + 0][lr] = bv[q].x; Bs[nxt][kb + 1][lr] = bv[q].y;
                Bs[nxt][kb + 2][lr] = bv[q].z; Bs[nxt][kb + 3][lr] = bv[q].w;
            }
        }
    }
    float* gbase = g_gx[dir] + (size_t)s * 1024 * 128;
#pragma unroll
    for (int i = 0; i < 8; i++) {
        const int col = ntile * 128 + tm * 8 + i;
        const float bb = bi[col] + bh[col];
        float2 v0 = upk2(acc2[i][0]), v1 = upk2(acc2[i][1]);
        float2 v2 = upk2(acc2[i][2]), v3 = upk2(acc2[i][3]);
        float4 oA = make_float4(v0.x + bb, v0.y + bb, v1.x + bb, v1.y + bb);
        float4 oB = make_float4(v2.x + bb, v2.y + bb, v3.x + bb, v3.y + bb);
        *(float4*)(gbase + (size_t)col * 128 + 4 * tn)      = oA;
        *(float4*)(gbase + (size_t)col * 128 + 64 + 4 * tn) = oB;
    }
}

// ---------------- kernel 3: persistent LSTM, direct-L2 h reads --------------
// 128 CTAs x 256 threads. CTA: dir=cta&1, units u0..u0+3. Lane l: ul=l>>3,
// bp=l&7; warp w owns batches [16w,16w+16). h read straight from L2 (ldcg,
// 64B/warp/k coalesced), software-pipelined 2x8k chunks in registers.
// Distributed-flag barrier: each CTA spins on its OWN 128B line.
__global__ __launch_bounds__(256) void lstm_persist()
{
    __shared__ unsigned long long wd[HDIM][4][4];   // dup'd weight pairs, 32KB

    const int cta = blockIdx.x;
    const int dir = cta & 1;
    const int u0  = (cta >> 1) * 4;
    const int t   = threadIdx.x;
    const int w   = t >> 5;
    const int l   = t & 31;
    const int ul  = l >> 3;
    const int bp  = l & 7;
    const int u   = u0 + ul;
    const int b0  = w * 16 + 2 * bp;

    for (int e = t; e < 256 * 16; e += 256) {
        int k = e >> 4, ui = (e >> 2) & 3, g = e & 3;
        float wv = g_Wt4[dir][k][u0 + ui][g];
        wd[k][ui][g] = pk2(wv, wv);
    }
    *(float2*)&g_h[dir][0][u][b0] = make_float2(0.f, 0.f);
    float c0 = 0.f, c1 = 0.f, h0v = 0.f, h1v = 0.f;
    __threadfence();
    __syncthreads();

    int epoch = 1;
    // initial barrier
    if (t < 32) {
        int v = 0;
        if (l == 0) v = atomicAdd(&g_bar_cnt, 1);
        v = __shfl_sync(0xffffffffu, v, 0);
        if (v == epoch * NCTA_LSTM - 1) {
#pragma unroll
            for (int j = 0; j < NCTA_LSTM / 32; j++) g_flags[l * (NCTA_LSTM / 32) + j][0] = epoch;
        } else if (l == 0) {
            while (g_flags[cta][0] < epoch) { }
            __threadfence();
        }
    }
    __syncthreads();

    const float* gxd = g_gx[dir];
    // prefetch gx for step 0
    float2 gxq[4];
#pragma unroll
    for (int g = 0; g < 4; g++)
        gxq[g] = __ldcg((const float2*)(gxd + ((size_t)0 * 1024 + g * 256 + u) * 128 + b0));

    for (int s = 0; s < S_LEN; s++) {
        const int buf = s & 1;
        const float* hb = &g_h[dir][buf][0][b0];    // stride 128 floats per k

        unsigned long long acc[4] = {0ULL, 0ULL, 0ULL, 0ULL};
        unsigned long long hpA[8], hpB[8];
#pragma unroll
        for (int i = 0; i < 8; i++) hpA[i] = __ldcg((const unsigned long long*)(hb + i * 128));
#pragma unroll
        for (int i = 0; i < 8; i++) hpB[i] = __ldcg((const unsigned long long*)(hb + (8 + i) * 128));

        for (int kc = 0; kc < 32; kc += 2) {
            const int kA = kc * 8, kB = kA + 8;
#pragma unroll
            for (int i = 0; i < 8; i++) {
                ulonglong2 wif = *(const ulonglong2*)&wd[kA + i][ul][0];
                ulonglong2 wgo = *(const ulonglong2*)&wd[kA + i][ul][2];
                fma2(acc[0], wif.x, hpA[i]); fma2(acc[1], wif.y, hpA[i]);
                fma2(acc[2], wgo.x, hpA[i]); fma2(acc[3], wgo.y, hpA[i]);
            }
            if (kc + 2 < 32) {
                const float* src = hb + (kc + 2) * 8 * 128;
#pragma unroll
                for (int i = 0; i < 8; i++) hpA[i] = __ldcg((const unsigned long long*)(src + i * 128));
            }
#pragma unroll
            for (int i = 0; i < 8; i++) {
                ulonglong2 wif = *(const ulonglong2*)&wd[kB + i][ul][0];
                ulonglong2 wgo = *(const ulonglong2*)&wd[kB + i][ul][2];
                fma2(acc[0], wif.x, hpB[i]); fma2(acc[1], wif.y, hpB[i]);
                fma2(acc[2], wgo.x, hpB[i]); fma2(acc[3], wgo.y, hpB[i]);
            }
            if (kc + 3 < 32) {
                const float* src = hb + (kc + 3) * 8 * 128;
#pragma unroll
                for (int i = 0; i < 8; i++) hpB[i] = __ldcg((const unsigned long long*)(src + i * 128));
            }
        }
        // cell update for 2 batches
        float2 vi = upk2(acc[0]), vf = upk2(acc[1]), vg = upk2(acc[2]), vo = upk2(acc[3]);
        {
            float gi = gxq[0].x + vi.x, gf = gxq[1].x + vf.x;
            float gg = gxq[2].x + vg.x, go = gxq[3].x + vo.x;
            float cc = sigmoidf_(gf) * c0 + sigmoidf_(gi) * tanhf_(gg);
            c0 = cc; h0v = sigmoidf_(go) * tanhf_(cc);
        }
        {
            float gi = gxq[0].y + vi.y, gf = gxq[1].y + vf.y;
            float gg = gxq[2].y + vg.y, go = gxq[3].y + vo.y;
            float cc = sigmoidf_(gf) * c1 + sigmoidf_(gi) * tanhf_(gg);
            c1 = cc; h1v = sigmoidf_(go) * tanhf_(cc);
        }
        __stcg((float2*)&g_h[dir][buf ^ 1][u][b0], make_float2(h0v, h1v));
        __threadfence();
        // prefetch gx for next step (hidden behind barrier latency)
        if (s + 1 < S_LEN) {
#pragma unroll
            for (int g = 0; g < 4; g++)
                gxq[g] = __ldcg((const float2*)(gxd + ((size_t)(s + 1) * 1024 + g * 256 + u) * 128 + b0));
        }
        __syncthreads();
        epoch++;
        if (t < 32) {
            int v = 0;
            if (l == 0) v = atomicAdd(&g_bar_cnt, 1);
            v = __shfl_sync(0xffffffffu, v, 0);
            if (v == epoch * NCTA_LSTM - 1) {
#pragma unroll
                for (int j = 0; j < NCTA_LSTM / 32; j++) g_flags[l * (NCTA_LSTM / 32) + j][0] = epoch;
            } else if (l == 0) {
                while (g_flags[cta][0] < epoch) { }
                __threadfence();
            }
        }
        __syncthreads();
    }
    g_h0[(size_t)b0 * (2 * HDIM) + dir * HDIM + u]       = h0v;
    g_h0[(size_t)(b0 + 1) * (2 * HDIM) + dir * HDIM + u] = h1v;
}

// ---------------- kernel 4: decoder input gates ------------------------------
__global__ __launch_bounds__(256) void dec_prep_kernel(
    const int* __restrict__ classes, const float* __restrict__ ecW,
    const float* __restrict__ dWih, const float* __restrict__ dbih)
{
    __shared__ float ce[EDIM];
    const int c = blockIdx.x;
    const int cls = classes[c];
    for (int e = threadIdx.x; e < EDIM; e += blockDim.x)
        ce[e] = tanhf_(ecW[(size_t)cls * EDIM + e]);
    __syncthreads();
    const int j = blockIdx.y * 256 + threadIdx.x;
    float acc = dbih[j];
    const float4* w = (const float4*)(dWih + (size_t)j * EDIM);
#pragma unroll 5
    for (int k = 0; k < EDIM / 4; k++) {
        float4 wv = w[k];
        acc += wv.x * ce[4 * k] + wv.y * ce[4 * k + 1] + wv.z * ce[4 * k + 2] + wv.w * ce[4 * k + 3];
    }
    g_gxc[c * 1536 + j] = acc;
}

// ---------------- kernel 5: decoder GRU + proj + cls + log_softmax ----------
__global__ __launch_bounds__(512) void dec_kernel(
    const float* __restrict__ dbhh,
    const float* __restrict__ projW, const float* __restrict__ projB,
    const float* __restrict__ clsW, const float* __restrict__ clsB,
    float* __restrict__ out)
{
    const int Gd = 2;
    const int H2 = 2 * HDIM;
    const int b0 = blockIdx.x * Gd;
    const int u  = threadIdx.x;
    const ulonglong2* W2 = (const ulonglong2*)&g_dWt4[0][0][0];

    __shared__ unsigned long long hd[2][Gd][512];
    __shared__ float hplain[Gd][512];
    __shared__ float projs[Gd][PDIM];
    __shared__ float lgs[Gd][2];

    float hprev[Gd];
#pragma unroll
    for (int b = 0; b < Gd; b++) {
        hprev[b] = g_h0[(size_t)(b0 + b) * H2 + u];
        hd[0][b][u] = pk2(hprev[b], hprev[b]);
    }
    const float bhr = dbhh[u], bhz = dbhh[H2 + u], bhn = dbhh[2 * H2 + u];
    __syncthreads();

    for (int c = 0; c < NCLS; c++) {
        const int cur = c & 1, nxt = cur ^ 1;
        unsigned long long arz[Gd], anp[Gd];
#pragma unroll
        for (int b = 0; b < Gd; b++) { arz[b] = 0ULL; anp[b] = 0ULL; }
        const unsigned long long* h0p = &hd[cur][0][0];
        const unsigned long long* h1p = &hd[cur][1][0];

#pragma unroll 4
        for (int k = 0; k < H2; k++) {
            ulonglong2 wv = W2[k * H2 + u];
            unsigned long long hh0 = h0p[k], hh1 = h1p[k];
            fma2(arz[0], wv.x, hh0); fma2(anp[0], wv.y, hh0);
            fma2(arz[1], wv.x, hh1); fma2(anp[1], wv.y, hh1);
        }
        const float gxr = g_gxc[c * 1536 + u];
        const float gxz = g_gxc[c * 1536 + H2 + u];
        const float gxn = g_gxc[c * 1536 + 2 * H2 + u];
#pragma unroll
        for (int b = 0; b < Gd; b++) {
            float2 vrz = upk2(arz[b]);
            float2 vnp = upk2(anp[b]);
            float r = sigmoidf_(gxr + vrz.x + bhr);
            float z = sigmoidf_(gxz + vrz.y + bhz);
            float n = tanhf_(gxn + r * (vnp.x + bhn));
            float hn = tanhf_((1.0f - z) * n + z * hprev[b]);
            hprev[b] = hn;
            hd[nxt][b][u] = pk2(hn, hn);
            hplain[b][u] = hn;
        }
        __syncthreads();
        {
            const int b = u >> 8, p = u & 255;
            const float4* wv = (const float4*)(projW + (size_t)p * H2);
            const float4* hv = (const float4*)hplain[b];
            float acc = projB[p];
            for (int k4 = 0; k4 < H2 / 4; k4++) {
                float4 w4 = wv[k4], h4 = hv[k4];
                acc += w4.x * h4.x + w4.y * h4.y + w4.z * h4.z + w4.w * h4.w;
            }
            projs[b][p] = acc;
        }
        __syncthreads();
        const int wid = u >> 5, lid = u & 31;
        if (wid < Gd * 2) {
            const int b = wid >> 1, cl = wid & 1;
            float acc = 0.0f;
            for (int k = lid; k < PDIM; k += 32) acc += clsW[cl * PDIM + k] * projs[b][k];
#pragma unroll
            for (int o = 16; o > 0; o >>= 1) acc += __shfl_down_sync(0xffffffffu, acc, o);
            if (lid == 0) lgs[b][cl] = acc + clsB[cl];
        }
        __syncthreads();
        if (u < Gd) {
            const int b = u;
            float l0 = lgs[b][0], l1 = lgs[b][1];
            float m = fmaxf(l0, l1);
            float lse = m + logf(expf(l0 - m) + expf(l1 - m));
            out[(size_t)c * BSZ * 2 + (b0 + b) * 2 + 0] = l0 - lse;
            out[(size_t)c * BSZ * 2 + (b0 + b) * 2 + 1] = l1 - lse;
        }
        __syncthreads();
    }
}

// ---------------- launch -----------------------------------------------------
extern "C" void kernel_launch(void* const* d_in, const int* in_sizes, int n_in,
                              void* d_out, int out_size)
{
    const int*   seq     = (const int*)d_in[0];
    const int*   classes = (const int*)d_in[1];
    const float* embW    = (const float*)d_in[2];
    const float* ecW     = (const float*)d_in[3];
    const float* fWih    = (const float*)d_in[4];
    const float* fWhh    = (const float*)d_in[5];
    const float* fbih    = (const float*)d_in[6];
    const float* fbhh    = (const float*)d_in[7];
    const float* bWih    = (const float*)d_in[8];
    const float* bWhh    = (const float*)d_in[9];
    const float* bbih    = (const float*)d_in[10];
    const float* bbhh    = (const float*)d_in[11];
    const float* dWih    = (const float*)d_in[12];
    const float* dWhh    = (const float*)d_in[13];
    const float* dbih    = (const float*)d_in[14];
    const float* dbhh    = (const float*)d_in[15];
    const float* projW   = (const float*)d_in[16];
    const float* projB   = (const float*)d_in[17];
    const float* clsW    = (const float*)d_in[18];
    const float* clsB    = (const float*)d_in[19];
    float* out = (float*)d_out;

    {   // 0. weight transposes + barrier reset
        dim3 gl(HDIM / 32, HDIM / 32, 8);
        transpose_lstm_w<<<gl, 1024>>>(fWhh, bWhh);
        dim3 gd(2 * HDIM / 32, 2 * HDIM / 32, 3);
        transpose_dec_w<<<gd, 1024>>>(dWhh);
    }
    {   // 1. embeddings
        long long total = (long long)S_LEN * BSZ * EDIM;
        int blocks = (int)((total + 255) / 256);
        embed_kernel<<<blocks, 256>>>(seq, embW);
    }
    {   // 2. input-gate GEMMs, double-buffered
        dim3 grid(S_LEN, 1024 / 128, 2);
        gx_gemm_kernel<<<grid, 256>>>(fWih, fbih, fbhh, bWih, bbih, bbhh);
    }
    {   // 3. persistent bidirectional LSTM (direct-L2 h, distributed barrier)
        lstm_persist<<<NCTA_LSTM, 256>>>();
    }
    {   // 4. decoder input gates per class
        dim3 grid(NCLS, 6);
        dec_prep_kernel<<<grid, 256>>>(classes, ecW, dWih, dbih);
    }
    {   // 5. decoder GRU + projection + classifier + log_softmax
        dec_kernel<<<BSZ / 2, 512>>>(dbhh, projW, projB, clsW, clsB, out);
    }
    (void)in_sizes; (void)n_in; (void)out_size;
}

// round 8
// speedup vs baseline: 1.0640x; 1.0640x over previous
#include <cuda_runtime.h>
#include <cuda_bf16.h>
#include <math.h>

#define S_LEN 512
#define BSZ   128
#define EDIM  300
#define HDIM  256
#define NCLS  6
#define PDIM  256
#define NCTA_LSTM 128            // 64 u-slice CTAs per direction

// ---------------- scratch (device globals; no runtime allocation) ----------
__device__ float g_seq_emb[(size_t)S_LEN * BSZ * EDIM];              // 78.6 MB
__device__ float g_gx[2][(size_t)S_LEN * 4 * HDIM * BSZ];            // [dir][s][col][b] 536 MB
__device__ float g_h[2][2][HDIM][BSZ];                               // [dir][buf][u][b]
__device__ float g_h0[(size_t)BSZ * 2 * HDIM];                       // concat [fh, bh]
__device__ float g_gxc[NCLS * 3 * 2 * HDIM];                         // decoder input gates
__device__ float g_Wt4[2][HDIM][HDIM][4];                            // [dir][k][u][gate i,f,g,o]
__device__ float g_dWt4[2 * HDIM][2 * HDIM][4];                      // [k][u][gate r,z,n,pad]
__device__ int   g_bar_cnt2[64];                                     // [dir*32] arrival counters
__device__ volatile int g_flags[2][64][32];                          // per-dir per-CTA release lines

// ---------------- helpers ---------------------------------------------------
__device__ __forceinline__ float sigmoidf_(float x) { return 1.0f / (1.0f + expf(-x)); }
__device__ __forceinline__ float tanhf_(float x) { return 1.0f - 2.0f / (expf(2.0f * x) + 1.0f); }

__device__ __forceinline__ unsigned long long pk2(float lo, float hi) {
    return ((unsigned long long)__float_as_uint(hi) << 32) | (unsigned long long)__float_as_uint(lo);
}
__device__ __forceinline__ float2 upk2(unsigned long long u) {
    float2 f; f.x = __uint_as_float((unsigned)u); f.y = __uint_as_float((unsigned)(u >> 32)); return f;
}
__device__ __forceinline__ void fma2(unsigned long long& d, unsigned long long a, unsigned long long b) {
    asm("fma.rn.f32x2 %0, %1, %2, %0;" : "+l"(d) : "l"(a), "l"(b));
}
__device__ __forceinline__ void add2(unsigned long long& d, unsigned long long a) {
    asm("add.rn.f32x2 %0, %0, %1;" : "+l"(d) : "l"(a));
}

// ---------------- kernel 0a: transpose LSTM Whh + reset barrier -------------
__global__ __launch_bounds__(1024) void transpose_lstm_w(const float* __restrict__ fWhh,
                                                         const float* __restrict__ bWhh)
{
    if (blockIdx.x == 0 && blockIdx.y == 0 && blockIdx.z == 0) {
        for (int i = threadIdx.x; i < 64; i += 1024) g_bar_cnt2[i] = 0;
        for (int i = threadIdx.x; i < 2 * 64 * 32; i += 1024) ((int*)g_flags)[i] = 0;
    }
    __shared__ float t[32][33];
    const int dir = blockIdx.z >> 2;
    const int g   = blockIdx.z & 3;
    const int k0  = blockIdx.x * 32;
    const int u0  = blockIdx.y * 32;
    const int tx = threadIdx.x & 31, ty = threadIdx.x >> 5;
    const float* W = dir ? bWhh : fWhh;
    t[ty][tx] = W[(size_t)(g * HDIM + u0 + ty) * HDIM + k0 + tx];
    __syncthreads();
    g_Wt4[dir][k0 + ty][u0 + tx][g] = t[tx][ty];
}

// ---------------- kernel 0b: transpose decoder Whh ---------------------------
__global__ __launch_bounds__(1024) void transpose_dec_w(const float* __restrict__ dWhh)
{
    __shared__ float t[32][33];
    const int g  = blockIdx.z;
    const int k0 = blockIdx.x * 32;
    const int u0 = blockIdx.y * 32;
    const int tx = threadIdx.x & 31, ty = threadIdx.x >> 5;
    t[ty][tx] = dWhh[(size_t)(g * 2 * HDIM + u0 + ty) * (2 * HDIM) + k0 + tx];
    __syncthreads();
    g_dWt4[k0 + ty][u0 + tx][g] = t[tx][ty];
}

// ---------------- kernel 1: embedding gather + tanh, time-major -------------
__global__ void embed_kernel(const int* __restrict__ seq, const float* __restrict__ embW) {
    long long idx = (long long)blockIdx.x * blockDim.x + threadIdx.x;
    const long long total = (long long)S_LEN * BSZ * EDIM;
    if (idx >= total) return;
    int e = (int)(idx % EDIM);
    int r = (int)(idx / EDIM);
    int b = r % BSZ;
    int s = r / BSZ;
    int v = seq[b * S_LEN + s];
    g_seq_emb[idx] = tanhf_(embW[(long long)v * EDIM + e]);
}

// ---------------- kernel 2: input GEMMs, double-buffered smem ---------------
__global__ __launch_bounds__(256) void gx_gemm_kernel(
    const float* __restrict__ fWih, const float* __restrict__ fbih, const float* __restrict__ fbhh,
    const float* __restrict__ bWih, const float* __restrict__ bbih, const float* __restrict__ bbhh)
{
    __shared__ float As[2][16][128];
    __shared__ float Bs[2][16][128];

    const int dir   = blockIdx.z;
    const int s     = blockIdx.x;
    const int ntile = blockIdx.y;
    const float* W  = dir ? bWih : fWih;
    const float* bi = dir ? bbih : fbih;
    const float* bh = dir ? bbhh : fbhh;
    const int src_s = dir ? ((S_LEN - s) & (S_LEN - 1)) : s;
    const float* Abase = g_seq_emb + (size_t)src_s * BSZ * EDIM;

    const int t   = threadIdx.x;
    const int lr  = t & 127;
    const int lqp = t >> 7;
    const int tm  = t >> 4;
    const int tn  = t & 15;

    unsigned long long acc2[8][4];
#pragma unroll
    for (int i = 0; i < 8; i++)
#pragma unroll
        for (int j = 0; j < 4; j++) acc2[i][j] = 0ULL;

    const int NK = (EDIM + 15) / 16;   // 19
    float4 av[2], bv[2];
#pragma unroll
    for (int q = 0; q < 2; q++) {
        const int kk = (lqp * 2 + q) * 4;
        av[q] = make_float4(0.f, 0.f, 0.f, 0.f);
        bv[q] = make_float4(0.f, 0.f, 0.f, 0.f);
        if (kk + 3 < EDIM) {
            av[q] = *(const float4*)(W + (size_t)(ntile * 128 + lr) * EDIM + kk);
            bv[q] = *(const float4*)(Abase + (size_t)lr * EDIM + kk);
        }
    }
#pragma unroll
    for (int q = 0; q < 2; q++) {
        const int kb = (lqp * 2 + q) * 4;
        As[0][kb + 0][lr] = av[q].x; As[0][kb + 1][lr] = av[q].y;
        As[0][kb + 2][lr] = av[q].z; As[0][kb + 3][lr] = av[q].w;
        Bs[0][kb + 0][lr] = bv[q].x; Bs[0][kb + 1][lr] = bv[q].y;
        Bs[0][kb + 2][lr] = bv[q].z; Bs[0][kb + 3][lr] = bv[q].w;
    }

    for (int kt = 0; kt < NK; kt++) {
        __syncthreads();
        const int cur = kt & 1;
        const bool more = (kt + 1 < NK);
        if (more) {
#pragma unroll
            for (int q = 0; q < 2; q++) {
                const int kk = (kt + 1) * 16 + (lqp * 2 + q) * 4;
                av[q] = make_float4(0.f, 0.f, 0.f, 0.f);
                bv[q] = make_float4(0.f, 0.f, 0.f, 0.f);
                if (kk + 3 < EDIM) {
                    av[q] = *(const float4*)(W + (size_t)(ntile * 128 + lr) * EDIM + kk);
                    bv[q] = *(const float4*)(Abase + (size_t)lr * EDIM + kk);
                }
            }
        }
#pragma unroll
        for (int k = 0; k < 16; k++) {
            float4 aA = *(const float4*)&As[cur][k][tm * 8];
            float4 aB = *(const float4*)&As[cur][k][tm * 8 + 4];
            ulonglong2 bA = *(const ulonglong2*)&Bs[cur][k][4 * tn];
            ulonglong2 bB = *(const ulonglong2*)&Bs[cur][k][64 + 4 * tn];
            unsigned long long a[8];
            a[0] = pk2(aA.x, aA.x); a[1] = pk2(aA.y, aA.y);
            a[2] = pk2(aA.z, aA.z); a[3] = pk2(aA.w, aA.w);
            a[4] = pk2(aB.x, aB.x); a[5] = pk2(aB.y, aB.y);
            a[6] = pk2(aB.z, aB.z); a[7] = pk2(aB.w, aB.w);
#pragma unroll
            for (int i = 0; i < 8; i++) {
                fma2(acc2[i][0], a[i], bA.x);
                fma2(acc2[i][1], a[i], bA.y);
                fma2(acc2[i][2], a[i], bB.x);
                fma2(acc2[i][3], a[i], bB.y);
            }
        }
        if (more) {
            const int nxt = cur ^ 1;
#pragma unroll
            for (int q = 0; q < 2; q++) {
                const int kb = (lqp * 2 + q) * 4;
                As[nxt][kb + 0][lr] = av[q].x; As[nxt][kb + 1][lr] = av[q].y;
                As[nxt][kb + 2][lr] = av[q].z; As[nxt][kb + 3][lr] = av[q].w;
                Bs[nxt][kb + 0][lr] = bv[q].x; Bs[nxt][kb + 1][lr] = bv[q].y;
                Bs[nxt][kb + 2][lr] = bv[q].z; Bs[nxt][kb + 3][lr] = bv[q].w;
            }
        }
    }
    float* gbase = g_gx[dir] + (size_t)s * 1024 * 128;
#pragma unroll
    for (int i = 0; i < 8; i++) {
        const int col = ntile * 128 + tm * 8 + i;
        const float bb = bi[col] + bh[col];
        float2 v0 = upk2(acc2[i][0]), v1 = upk2(acc2[i][1]);
        float2 v2 = upk2(acc2[i][2]), v3 = upk2(acc2[i][3]);
        float4 oA = make_float4(v0.x + bb, v0.y + bb, v1.x + bb, v1.y + bb);
        float4 oB = make_float4(v2.x + bb, v2.y + bb, v3.x + bb, v3.y + bb);
        *(float4*)(gbase + (size_t)col * 128 + 4 * tn)      = oA;
        *(float4*)(gbase + (size_t)col * 128 + 64 + 4 * tn) = oB;
    }
}

// ---------------- kernel 3: persistent LSTM, 512 threads, k-split -----------
// 128 CTAs x 512 threads. CTA: dir=cta>>6, units u0..u0+3. Warp w: ks=w>>3
// (k half), wb=w&7 (batch group). Lane: ul=l>>3, bp=l&7. Warps 8-15 store
// partial sums to smem; warps 0-7 combine (packed f32x2 add) + cell update.
// Per-direction distributed-flag barrier (64 arrivals).
__global__ __launch_bounds__(512) void lstm_persist()
{
    __shared__ unsigned long long wd[HDIM][4][4];   // dup'd weight pairs, 32KB
    __shared__ unsigned long long part[8][32][4];   // kslice-1 partials, 8KB

    const int cta = blockIdx.x;
    const int dir = cta >> 6;
    const int cl  = cta & 63;
    const int u0  = cl * 4;
    const int t   = threadIdx.x;
    const int w   = t >> 5;
    const int l   = t & 31;
    const int ks  = w >> 3;             // k slice 0/1
    const int wb  = w & 7;              // batch group
    const int ul  = l >> 3;             // unit 0..3
    const int bp  = l & 7;              // batch pair
    const int u   = u0 + ul;
    const int b0  = wb * 16 + 2 * bp;
    const int kbase = ks * 128;

    for (int e = t; e < 256 * 16; e += 512) {
        int k = e >> 4, ui = (e >> 2) & 3, g = e & 3;
        float wv = g_Wt4[dir][k][u0 + ui][g];
        wd[k][ui][g] = pk2(wv, wv);
    }
    float c0 = 0.f, c1 = 0.f, h0v = 0.f, h1v = 0.f;
    if (ks == 0) *(float2*)&g_h[dir][0][u][b0] = make_float2(0.f, 0.f);
    __threadfence();
    __syncthreads();

    int epoch = 1;
    if (t < 32) {
        int v = 0;
        if (l == 0) v = atomicAdd(&g_bar_cnt2[dir * 32], 1);
        v = __shfl_sync(0xffffffffu, v, 0);
        if (v == epoch * 64 - 1) {
            g_flags[dir][l][0] = epoch;
            g_flags[dir][l + 32][0] = epoch;
        } else if (l == 0) {
            while (g_flags[dir][cl][0] < epoch) { }
            __threadfence();
        }
    }
    __syncthreads();

    const float* gxd = g_gx[dir];
    float2 gxq[4];
    if (ks == 0) {
#pragma unroll
        for (int g = 0; g < 4; g++)
            gxq[g] = __ldcg((const float2*)(gxd + ((size_t)0 * 1024 + g * 256 + u) * 128 + b0));
    }

    for (int s = 0; s < S_LEN; s++) {
        const int buf = s & 1;
        const float* hb = &g_h[dir][buf][0][0] + kbase * 128 + b0;   // 128 rows, stride 128

        unsigned long long acc[4] = {0ULL, 0ULL, 0ULL, 0ULL};
        unsigned long long hpA[8], hpB[8];
#pragma unroll
        for (int i = 0; i < 8; i++) hpA[i] = __ldcg((const unsigned long long*)(hb + i * 128));
#pragma unroll
        for (int i = 0; i < 8; i++) hpB[i] = __ldcg((const unsigned long long*)(hb + (8 + i) * 128));

        for (int kc = 0; kc < 16; kc += 2) {
            const int kA = kbase + kc * 8, kB = kA + 8;
#pragma unroll
            for (int i = 0; i < 8; i++) {
                ulonglong2 wif = *(const ulonglong2*)&wd[kA + i][ul][0];
                ulonglong2 wgo = *(const ulonglong2*)&wd[kA + i][ul][2];
                fma2(acc[0], wif.x, hpA[i]); fma2(acc[1], wif.y, hpA[i]);
                fma2(acc[2], wgo.x, hpA[i]); fma2(acc[3], wgo.y, hpA[i]);
            }
            if (kc + 2 < 16) {
                const float* src = hb + (kc + 2) * 8 * 128;
#pragma unroll
                for (int i = 0; i < 8; i++) hpA[i] = __ldcg((const unsigned long long*)(src + i * 128));
            }
#pragma unroll
            for (int i = 0; i < 8; i++) {
                ulonglong2 wif = *(const ulonglong2*)&wd[kB + i][ul][0];
                ulonglong2 wgo = *(const ulonglong2*)&wd[kB + i][ul][2];
                fma2(acc[0], wif.x, hpB[i]); fma2(acc[1], wif.y, hpB[i]);
                fma2(acc[2], wgo.x, hpB[i]); fma2(acc[3], wgo.y, hpB[i]);
            }
            if (kc + 3 < 16) {
                const float* src = hb + (kc + 3) * 8 * 128;
#pragma unroll
                for (int i = 0; i < 8; i++) hpB[i] = __ldcg((const unsigned long long*)(src + i * 128));
            }
        }
        if (ks == 1) {
            *(ulonglong2*)&part[wb][l][0] = make_ulonglong2(acc[0], acc[1]);
            *(ulonglong2*)&part[wb][l][2] = make_ulonglong2(acc[2], acc[3]);
        }
        __syncthreads();
        if (ks == 0) {
            ulonglong2 p01 = *(const ulonglong2*)&part[wb][l][0];
            ulonglong2 p23 = *(const ulonglong2*)&part[wb][l][2];
            add2(acc[0], p01.x); add2(acc[1], p01.y);
            add2(acc[2], p23.x); add2(acc[3], p23.y);
            float2 vi = upk2(acc[0]), vf = upk2(acc[1]), vg = upk2(acc[2]), vo = upk2(acc[3]);
            {
                float gi = gxq[0].x + vi.x, gf = gxq[1].x + vf.x;
                float gg = gxq[2].x + vg.x, go = gxq[3].x + vo.x;
                float cc = sigmoidf_(gf) * c0 + sigmoidf_(gi) * tanhf_(gg);
                c0 = cc; h0v = sigmoidf_(go) * tanhf_(cc);
            }
            {
                float gi = gxq[0].y + vi.y, gf = gxq[1].y + vf.y;
                float gg = gxq[2].y + vg.y, go = gxq[3].y + vo.y;
                float cc = sigmoidf_(gf) * c1 + sigmoidf_(gi) * tanhf_(gg);
                c1 = cc; h1v = sigmoidf_(go) * tanhf_(cc);
            }
            __stcg((float2*)&g_h[dir][buf ^ 1][u][b0], make_float2(h0v, h1v));
            if (s + 1 < S_LEN) {
#pragma unroll
                for (int g = 0; g < 4; g++)
                    gxq[g] = __ldcg((const float2*)(gxd + ((size_t)(s + 1) * 1024 + g * 256 + u) * 128 + b0));
            }
            __threadfence();
        }
        __syncthreads();
        epoch++;
        if (t < 32) {
            int v = 0;
            if (l == 0) v = atomicAdd(&g_bar_cnt2[dir * 32], 1);
            v = __shfl_sync(0xffffffffu, v, 0);
            if (v == epoch * 64 - 1) {
                g_flags[dir][l][0] = epoch;
                g_flags[dir][l + 32][0] = epoch;
            } else if (l == 0) {
                while (g_flags[dir][cl][0] < epoch) { }
                __threadfence();
            }
        }
        __syncthreads();
    }
    if (ks == 0) {
        g_h0[(size_t)b0 * (2 * HDIM) + dir * HDIM + u]       = h0v;
        g_h0[(size_t)(b0 + 1) * (2 * HDIM) + dir * HDIM + u] = h1v;
    }
}

// ---------------- kernel 4: decoder input gates ------------------------------
__global__ __launch_bounds__(256) void dec_prep_kernel(
    const int* __restrict__ classes, const float* __restrict__ ecW,
    const float* __restrict__ dWih, const float* __restrict__ dbih)
{
    __shared__ float ce[EDIM];
    const int c = blockIdx.x;
    const int cls = classes[c];
    for (int e = threadIdx.x; e < EDIM; e += blockDim.x)
        ce[e] = tanhf_(ecW[(size_t)cls * EDIM + e]);
    __syncthreads();
    const int j = blockIdx.y * 256 + threadIdx.x;
    float acc = dbih[j];
    const float4* w = (const float4*)(dWih + (size_t)j * EDIM);
#pragma unroll 5
    for (int k = 0; k < EDIM / 4; k++) {
        float4 wv = w[k];
        acc += wv.x * ce[4 * k] + wv.y * ce[4 * k + 1] + wv.z * ce[4 * k + 2] + wv.w * ce[4 * k + 3];
    }
    g_gxc[c * 1536 + j] = acc;
}

// ---------------- kernel 5: decoder GRU + proj + cls + log_softmax ----------
__global__ __launch_bounds__(512) void dec_kernel(
    const float* __restrict__ dbhh,
    const float* __restrict__ projW, const float* __restrict__ projB,
    const float* __restrict__ clsW, const float* __restrict__ clsB,
    float* __restrict__ out)
{
    const int Gd = 2;
    const int H2 = 2 * HDIM;
    const int b0 = blockIdx.x * Gd;
    const int u  = threadIdx.x;
    const ulonglong2* W2 = (const ulonglong2*)&g_dWt4[0][0][0];

    __shared__ unsigned long long hd[2][Gd][512];
    __shared__ float hplain[Gd][512];
    __shared__ float projs[Gd][PDIM];
    __shared__ float lgs[Gd][2];

    float hprev[Gd];
#pragma unroll
    for (int b = 0; b < Gd; b++) {
        hprev[b] = g_h0[(size_t)(b0 + b) * H2 + u];
        hd[0][b][u] = pk2(hprev[b], hprev[b]);
    }
    const float bhr = dbhh[u], bhz = dbhh[H2 + u], bhn = dbhh[2 * H2 + u];
    __syncthreads();

    for (int c = 0; c < NCLS; c++) {
        const int cur = c & 1, nxt = cur ^ 1;
        unsigned long long arz[Gd], anp[Gd];
#pragma unroll
        for (int b = 0; b < Gd; b++) { arz[b] = 0ULL; anp[b] = 0ULL; }
        const unsigned long long* h0p = &hd[cur][0][0];
        const unsigned long long* h1p = &hd[cur][1][0];

#pragma unroll 4
        for (int k = 0; k < H2; k++) {
            ulonglong2 wv = W2[k * H2 + u];
            unsigned long long hh0 = h0p[k], hh1 = h1p[k];
            fma2(arz[0], wv.x, hh0); fma2(anp[0], wv.y, hh0);
            fma2(arz[1], wv.x, hh1); fma2(anp[1], wv.y, hh1);
        }
        const float gxr = g_gxc[c * 1536 + u];
        const float gxz = g_gxc[c * 1536 + H2 + u];
        const float gxn = g_gxc[c * 1536 + 2 * H2 + u];
#pragma unroll
        for (int b = 0; b < Gd; b++) {
            float2 vrz = upk2(arz[b]);
            float2 vnp = upk2(anp[b]);
            float r = sigmoidf_(gxr + vrz.x + bhr);
            float z = sigmoidf_(gxz + vrz.y + bhz);
            float n = tanhf_(gxn + r * (vnp.x + bhn));
            float hn = tanhf_((1.0f - z) * n + z * hprev[b]);
            hprev[b] = hn;
            hd[nxt][b][u] = pk2(hn, hn);
            hplain[b][u] = hn;
        }
        __syncthreads();
        {
            const int b = u >> 8, p = u & 255;
            const float4* wv = (const float4*)(projW + (size_t)p * H2);
            const float4* hv = (const float4*)hplain[b];
            float acc = projB[p];
            for (int k4 = 0; k4 < H2 / 4; k4++) {
                float4 w4 = wv[k4], h4 = hv[k4];
                acc += w4.x * h4.x + w4.y * h4.y + w4.z * h4.z + w4.w * h4.w;
            }
            projs[b][p] = acc;
        }
        __syncthreads();
        const int wid = u >> 5, lid = u & 31;
        if (wid < Gd * 2) {
            const int b = wid >> 1, cl = wid & 1;
            float acc = 0.0f;
            for (int k = lid; k < PDIM; k += 32) acc += clsW[cl * PDIM + k] * projs[b][k];
#pragma unroll
            for (int o = 16; o > 0; o >>= 1) acc += __shfl_down_sync(0xffffffffu, acc, o);
            if (lid == 0) lgs[b][cl] = acc + clsB[cl];
        }
        __syncthreads();
        if (u < Gd) {
            const int b = u;
            float l0 = lgs[b][0], l1 = lgs[b][1];
            float m = fmaxf(l0, l1);
            float lse = m + logf(expf(l0 - m) + expf(l1 - m));
            out[(size_t)c * BSZ * 2 + (b0 + b) * 2 + 0] = l0 - lse;
            out[(size_t)c * BSZ * 2 + (b0 + b) * 2 + 1] = l1 - lse;
        }
        __syncthreads();
    }
}

// ---------------- launch -----------------------------------------------------
extern "C" void kernel_launch(void* const* d_in, const int* in_sizes, int n_in,
                              void* d_out, int out_size)
{
    const int*   seq     = (const int*)d_in[0];
    const int*   classes = (const int*)d_in[1];
    const float* embW    = (const float*)d_in[2];
    const float* ecW     = (const float*)d_in[3];
    const float* fWih    = (const float*)d_in[4];
    const float* fWhh    = (const float*)d_in[5];
    const float* fbih    = (const float*)d_in[6];
    const float* fbhh    = (const float*)d_in[7];
    const float* bWih    = (const float*)d_in[8];
    const float* bWhh    = (const float*)d_in[9];
    const float* bbih    = (const float*)d_in[10];
    const float* bbhh    = (const float*)d_in[11];
    const float* dWih    = (const float*)d_in[12];
    const float* dWhh    = (const float*)d_in[13];
    const float* dbih    = (const float*)d_in[14];
    const float* dbhh    = (const float*)d_in[15];
    const float* projW   = (const float*)d_in[16];
    const float* projB   = (const float*)d_in[17];
    const float* clsW    = (const float*)d_in[18];
    const float* clsB    = (const float*)d_in[19];
    float* out = (float*)d_out;

    {   // 0. weight transposes + barrier reset
        dim3 gl(HDIM / 32, HDIM / 32, 8);
        transpose_lstm_w<<<gl, 1024>>>(fWhh, bWhh);
        dim3 gd(2 * HDIM / 32, 2 * HDIM / 32, 3);
        transpose_dec_w<<<gd, 1024>>>(dWhh);
    }
    {   // 1. embeddings
        long long total = (long long)S_LEN * BSZ * EDIM;
        int blocks = (int)((total + 255) / 256);
        embed_kernel<<<blocks, 256>>>(seq, embW);
    }
    {   // 2. input-gate GEMMs, double-buffered
        dim3 grid(S_LEN, 1024 / 128, 2);
        gx_gemm_kernel<<<grid, 256>>>(fWih, fbih, fbhh, bWih, bbih, bbhh);
    }
    {   // 3. persistent bidirectional LSTM (512 threads, k-split)
        lstm_persist<<<NCTA_LSTM, 512>>>();
    }
    {   // 4. decoder input gates per class
        dim3 grid(NCLS, 6);
        dec_prep_kernel<<<grid, 256>>>(classes, ecW, dWih, dbih);
    }
    {   // 5. decoder GRU + projection + classifier + log_softmax
        dec_kernel<<<BSZ / 2, 512>>>(dbhh, projW, projB, clsW, clsB, out);
    }
    (void)in_sizes; (void)n_in; (void)out_size;
}